// round 1
// baseline (speedup 1.0000x reference)
#include <cuda_runtime.h>
#include <cuda_bf16.h>
#include <cstdint>
#include <math.h>

#define TOKENS 8192
#define HDIM   1024
#define NOSC   64
#define TWO_N  128
#define SEQ    2048

// ---------------- scratch (static device memory; no allocations) ----------------
static __device__ __nv_bfloat16 g_xb [TOKENS * HDIM];
static __device__ __nv_bfloat16 g_h  [TOKENS * HDIM];
static __device__ __nv_bfloat16 g_h2 [TOKENS * HDIM];
static __device__ float         g_osc[TOKENS * TWO_N];
static __device__ __nv_bfloat16 g_comb[TOKENS * TWO_N];
static __device__ __nv_bfloat16 g_W1b[HDIM * HDIM];
static __device__ __nv_bfloat16 g_W2b[HDIM * TWO_N];
static __device__ __nv_bfloat16 g_W3b[TWO_N * HDIM];
static __device__ __nv_bfloat16 g_W4b[HDIM * HDIM];
static __device__ float         g_csum[NOSC];

// ---------------- small helpers ----------------
__device__ __forceinline__ void cp_async16(void* s, const void* g) {
    uint32_t sa = (uint32_t)__cvta_generic_to_shared(s);
    asm volatile("cp.async.cg.shared.global [%0], [%1], 16;\n" :: "r"(sa), "l"(g));
}

__device__ __forceinline__ void ldmatrix_x4(uint32_t* r, const void* p) {
    uint32_t a = (uint32_t)__cvta_generic_to_shared(p);
    asm volatile("ldmatrix.sync.aligned.m8n8.x4.shared.b16 {%0,%1,%2,%3}, [%4];\n"
        : "=r"(r[0]), "=r"(r[1]), "=r"(r[2]), "=r"(r[3]) : "r"(a));
}

__device__ __forceinline__ void ldmatrix_x4_trans(uint32_t* r, const void* p) {
    uint32_t a = (uint32_t)__cvta_generic_to_shared(p);
    asm volatile("ldmatrix.sync.aligned.m8n8.x4.trans.shared.b16 {%0,%1,%2,%3}, [%4];\n"
        : "=r"(r[0]), "=r"(r[1]), "=r"(r[2]), "=r"(r[3]) : "r"(a));
}

__device__ __forceinline__ void mma16816(float* d, const uint32_t* a, uint32_t b0, uint32_t b1) {
    asm volatile(
        "mma.sync.aligned.m16n8k16.row.col.f32.bf16.bf16.f32 "
        "{%0,%1,%2,%3}, {%4,%5,%6,%7}, {%8,%9}, {%0,%1,%2,%3};\n"
        : "+f"(d[0]), "+f"(d[1]), "+f"(d[2]), "+f"(d[3])
        : "r"(a[0]), "r"(a[1]), "r"(a[2]), "r"(a[3]), "r"(b0), "r"(b1));
}

// ---------------- f32 -> bf16 convert ----------------
__global__ void k_convert(const float* __restrict__ in, __nv_bfloat16* __restrict__ out, int n) {
    int i = (blockIdx.x * blockDim.x + threadIdx.x) * 4;
    if (i < n) {
        float4 v = *reinterpret_cast<const float4*>(in + i);
        *reinterpret_cast<__nv_bfloat162*>(out + i)     = __floats2bfloat162_rn(v.x, v.y);
        *reinterpret_cast<__nv_bfloat162*>(out + i + 2) = __floats2bfloat162_rn(v.z, v.w);
    }
}

// ---------------- coupling row-sum ----------------
__global__ void k_csum(const float* __restrict__ coupling) {
    int m = threadIdx.x;   // 64 threads
    float s = 0.f;
    #pragma unroll
    for (int j = 0; j < NOSC; j++) s += coupling[m * NOSC + j];
    g_csum[m] = s;
}

// ---------------- oscillator dynamics ----------------
// One block (64 threads) per token. O(N) coupling via sin/cos factorization.
__global__ void k_dynamics(const float* __restrict__ t, const float* __restrict__ Wt,
                           const float* __restrict__ bt, const float* __restrict__ freq,
                           const float* __restrict__ mu_p) {
    const int tok = blockIdx.x;
    const int i = threadIdx.x;            // oscillator id 0..63
    const int s = tok & (SEQ - 1);
    __nv_bfloat16* out = g_comb + (size_t)tok * TWO_N;

    if (s == 0) {
        // passthrough: combined[0] = [phase(0), amp(0)]
        float p = g_osc[(size_t)tok * TWO_N + i];
        float a = g_osc[(size_t)tok * TWO_N + NOSC + i];
        out[i]        = __float2bfloat16(p);
        out[NOSC + i] = __float2bfloat16(a);
        return;
    }

    const float* prev = g_osc + (size_t)(tok - 1) * TWO_N;
    float p = prev[i];
    float a = prev[NOSC + i];
    float sp, cp;
    sincosf(p, &sp, &cp);

    float cs = g_csum[i];
    float vc = cs * cp;   // csum[m]*cos(p_m)
    float vs = cs * sp;   // csum[m]*sin(p_m)

    __shared__ float shc[2], shs[2];
    #pragma unroll
    for (int o = 16; o > 0; o >>= 1) {
        vc += __shfl_down_sync(0xffffffffu, vc, o);
        vs += __shfl_down_sync(0xffffffffu, vs, o);
    }
    if ((i & 31) == 0) { shc[i >> 5] = vc; shs[i >> 5] = vs; }
    __syncthreads();
    float Sc = shc[0] + shc[1];
    float Ss = shs[0] + shs[1];

    float coupling_sum = sp * Sc - cp * Ss;
    float tmod   = t[tok] * Wt[i] + bt[i];
    float dphase = freq[i] + coupling_sum * 0.1f + tmod * 0.1f;
    float pn = p + dphase * 0.1f;

    float mu = *mu_p;
    float damp = (mu - 0.1f) * a - a * a * a;
    float an = tanhf(a + damp * 0.1f);   // * AMP_SAT(1.0)

    out[i]        = __float2bfloat16(pn);
    out[NOSC + i] = __float2bfloat16(an);
}

// ---------------- tiled bf16 MMA GEMM ----------------
// C[M,N] = A[M,K] (row-major bf16) @ B[K,N] (row-major bf16), fp32 accum.
// EPI: 0 = +bias, leaky_relu(0.2), bf16 out
//      1 = +bias, f32 out
//      2 = +bias, out = resid + 0.1*acc, f32 out
#define BM 128
#define BN 128
#define BK 32
#define ASTRIDE 40    // 80B row stride  (== 16 mod 128 -> conflict-free ldmatrix)
#define BSTRIDE 136   // 272B row stride (== 16 mod 128)

template <int EPI>
__global__ __launch_bounds__(256, 2)
void k_gemm(const __nv_bfloat16* __restrict__ A, const __nv_bfloat16* __restrict__ B,
            const float* __restrict__ bias, void* __restrict__ outp,
            const float* __restrict__ resid, int M, int N, int K) {
    __shared__ __align__(16) __nv_bfloat16 As[2][BM][ASTRIDE];
    __shared__ __align__(16) __nv_bfloat16 Bs[2][BK][BSTRIDE];

    const int tid  = threadIdx.x;
    const int lane = tid & 31;
    const int warp = tid >> 5;
    const int wm = warp >> 2;   // 0..1 : 64 rows each
    const int wn = warp & 3;    // 0..3 : 32 cols each
    const int bm0 = blockIdx.y * BM;
    const int bn0 = blockIdx.x * BN;

    float acc[4][4][4];
    #pragma unroll
    for (int a = 0; a < 4; a++)
        #pragma unroll
        for (int b = 0; b < 4; b++)
            #pragma unroll
            for (int c = 0; c < 4; c++) acc[a][b][c] = 0.f;

    const int KT = K / BK;

    auto load_tile = [&](int kt, int buf) {
        #pragma unroll
        for (int it = 0; it < 2; it++) {           // A: 128x32 bf16 = 8KB
            int c = tid + it * 256;
            int r = c >> 2, ch = c & 3;
            cp_async16(&As[buf][r][ch * 8], A + (size_t)(bm0 + r) * K + kt * BK + ch * 8);
        }
        #pragma unroll
        for (int it = 0; it < 2; it++) {           // B: 32x128 bf16 = 8KB
            int c = tid + it * 256;
            int r = c >> 4, ch = c & 15;
            cp_async16(&Bs[buf][r][ch * 8], B + (size_t)(kt * BK + r) * N + bn0 + ch * 8);
        }
        asm volatile("cp.async.commit_group;\n" ::: "memory");
    };

    load_tile(0, 0);

    for (int kt = 0; kt < KT; kt++) {
        const int buf = kt & 1;
        asm volatile("cp.async.wait_group 0;\n" ::: "memory");
        __syncthreads();
        if (kt + 1 < KT) load_tile(kt + 1, buf ^ 1);

        #pragma unroll
        for (int kk = 0; kk < 2; kk++) {       // two k16 steps per BK=32 tile
            uint32_t afr[4][4];
            #pragma unroll
            for (int im = 0; im < 4; im++)
                ldmatrix_x4(afr[im],
                    &As[buf][wm * 64 + im * 16 + (lane & 15)][kk * 16 + (lane >> 4) * 8]);
            uint32_t bfr[2][4];
            #pragma unroll
            for (int ip = 0; ip < 2; ip++)
                ldmatrix_x4_trans(bfr[ip],
                    &Bs[buf][kk * 16 + (lane & 15)][wn * 32 + ip * 16 + (lane >> 4) * 8]);
            #pragma unroll
            for (int im = 0; im < 4; im++)
                #pragma unroll
                for (int in = 0; in < 4; in++)
                    mma16816(acc[im][in], afr[im],
                             bfr[in >> 1][(in & 1) * 2], bfr[in >> 1][(in & 1) * 2 + 1]);
        }
    }

    // epilogue
    #pragma unroll
    for (int im = 0; im < 4; im++) {
        const int r0 = bm0 + wm * 64 + im * 16 + (lane >> 2);
        #pragma unroll
        for (int in = 0; in < 4; in++) {
            const int c0 = bn0 + wn * 32 + in * 8 + (lane & 3) * 2;
            const float bv0 = bias[c0], bv1 = bias[c0 + 1];
            #pragma unroll
            for (int half = 0; half < 2; half++) {
                const int r = r0 + half * 8;
                float v0 = acc[im][in][half * 2 + 0] + bv0;
                float v1 = acc[im][in][half * 2 + 1] + bv1;
                if (EPI == 0) {
                    v0 = v0 >= 0.f ? v0 : 0.2f * v0;
                    v1 = v1 >= 0.f ? v1 : 0.2f * v1;
                    *reinterpret_cast<__nv_bfloat162*>(
                        (__nv_bfloat16*)outp + (size_t)r * N + c0) = __floats2bfloat162_rn(v0, v1);
                } else if (EPI == 1) {
                    float2 o; o.x = v0; o.y = v1;
                    *reinterpret_cast<float2*>((float*)outp + (size_t)r * N + c0) = o;
                } else {
                    float2 xv = *reinterpret_cast<const float2*>(resid + (size_t)r * N + c0);
                    float2 o; o.x = xv.x + 0.1f * v0; o.y = xv.y + 0.1f * v1;
                    *reinterpret_cast<float2*>((float*)outp + (size_t)r * N + c0) = o;
                }
            }
        }
    }
}

// ---------------- launch ----------------
extern "C" void kernel_launch(void* const* d_in, const int* in_sizes, int n_in,
                              void* d_out, int out_size) {
    const float* x        = (const float*)d_in[0];
    const float* t        = (const float*)d_in[1];
    const float* W1       = (const float*)d_in[2];
    const float* b1       = (const float*)d_in[3];
    const float* W2       = (const float*)d_in[4];
    const float* b2       = (const float*)d_in[5];
    const float* W3       = (const float*)d_in[6];
    const float* b3       = (const float*)d_in[7];
    const float* W4       = (const float*)d_in[8];
    const float* b4       = (const float*)d_in[9];
    const float* Wt       = (const float*)d_in[10];
    const float* bt       = (const float*)d_in[11];
    const float* coupling = (const float*)d_in[12];
    const float* freq     = (const float*)d_in[13];
    const float* mu       = (const float*)d_in[14];
    float* out = (float*)d_out;

    void *p_xb, *p_h, *p_h2, *p_osc, *p_comb, *p_W1, *p_W2, *p_W3, *p_W4;
    cudaGetSymbolAddress(&p_xb,  g_xb);
    cudaGetSymbolAddress(&p_h,   g_h);
    cudaGetSymbolAddress(&p_h2,  g_h2);
    cudaGetSymbolAddress(&p_osc, g_osc);
    cudaGetSymbolAddress(&p_comb, g_comb);
    cudaGetSymbolAddress(&p_W1,  g_W1b);
    cudaGetSymbolAddress(&p_W2,  g_W2b);
    cudaGetSymbolAddress(&p_W3,  g_W3b);
    cudaGetSymbolAddress(&p_W4,  g_W4b);

    // converts (cheap, re-done each call for determinism)
    k_convert<<<TOKENS * HDIM / 1024, 256>>>(x,  (__nv_bfloat16*)p_xb, TOKENS * HDIM);
    k_convert<<<HDIM * HDIM   / 1024, 256>>>(W1, (__nv_bfloat16*)p_W1, HDIM * HDIM);
    k_convert<<<HDIM * TWO_N  / 1024, 256>>>(W2, (__nv_bfloat16*)p_W2, HDIM * TWO_N);
    k_convert<<<TWO_N * HDIM  / 1024, 256>>>(W3, (__nv_bfloat16*)p_W3, TWO_N * HDIM);
    k_convert<<<HDIM * HDIM   / 1024, 256>>>(W4, (__nv_bfloat16*)p_W4, HDIM * HDIM);
    k_csum<<<1, NOSC>>>(coupling);

    dim3 gBig(HDIM / BN, TOKENS / BM);    // (8, 64)
    dim3 gOsc(TWO_N / BN, TOKENS / BM);   // (1, 64)

    // h = lrelu(x @ W1 + b1)
    k_gemm<0><<<gBig, 256>>>((const __nv_bfloat16*)p_xb, (const __nv_bfloat16*)p_W1,
                             b1, p_h, nullptr, TOKENS, HDIM, HDIM);
    // osc = h @ W2 + b2
    k_gemm<1><<<gOsc, 256>>>((const __nv_bfloat16*)p_h, (const __nv_bfloat16*)p_W2,
                             b2, p_osc, nullptr, TOKENS, TWO_N, HDIM);
    // oscillator dynamics -> combined (bf16)
    k_dynamics<<<TOKENS, NOSC>>>(t, Wt, bt, freq, mu);
    // h2 = lrelu(combined @ W3 + b3)
    k_gemm<0><<<gBig, 256>>>((const __nv_bfloat16*)p_comb, (const __nv_bfloat16*)p_W3,
                             b3, p_h2, nullptr, TOKENS, HDIM, TWO_N);
    // out = x + 0.1*(h2 @ W4 + b4)
    k_gemm<2><<<gBig, 256>>>((const __nv_bfloat16*)p_h2, (const __nv_bfloat16*)p_W4,
                             b4, out, x, TOKENS, HDIM, HDIM);
}